// round 5
// baseline (speedup 1.0000x reference)
#include <cuda_runtime.h>
#include <cuda_bf16.h>
#include <cstdint>

#define NREG     10000
#define NBINS    32
#define NBUCKETS 128
#define PTS      8          // points per thread in eval

// Scratch (device globals are the sanctioned scratch mechanism).
// Bin struct (16 B): {bl_l, cdf_l, h_l, A = (h_r - h_l)/w}
__device__ __align__(16) float4 g_bins16[NREG * NBINS];        // 5.12 MB
// Bucket-direct table: bucket b holds the struct of the UPPER-BOUND bin for
// x in [b/128, (b+1)/128), with that bin's index k packed into the low 5
// mantissa bits of A (recovered for backward refinement).
__device__ __align__(16) float4 g_buckets[NREG * NBUCKETS];    // 20.48 MB

// ---------------------------------------------------------------------------
// Kernel 1: one warp per region. Softmax widths, normalized heights, scans,
// then writes the 32-entry bin table and the 128-entry bucket-direct table.
// ---------------------------------------------------------------------------
__global__ void __launch_bounds__(256)
spline_prep_kernel(const float* __restrict__ uw, const float* __restrict__ uh)
{
    __shared__ float  s_bl[8][33];
    __shared__ float4 s_e[8][32];

    const int warp = threadIdx.x >> 5;
    const int lane = threadIdx.x & 31;
    const int r    = blockIdx.x * 8 + warp;
    if (r >= NREG) return;

    const float w_logit = uw[r * NBINS + lane];
    const float h_logit = uh[r * (NBINS + 1) + lane];
    const float h_last  = uh[r * (NBINS + 1) + NBINS];

    // --- softmax over widths ---
    float m = w_logit;
    #pragma unroll
    for (int o = 16; o; o >>= 1) m = fmaxf(m, __shfl_xor_sync(0xffffffffu, m, o));
    float e = __expf(w_logit - m);
    float s = e;
    #pragma unroll
    for (int o = 16; o; o >>= 1) s += __shfl_xor_sync(0xffffffffu, s, o);
    const float w = e / s;

    // --- heights: exp, normalize by trapezoid area ---
    float hexp   = __expf(h_logit);
    float hexp_n = __shfl_down_sync(0xffffffffu, hexp, 1);
    if (lane == 31) hexp_n = __expf(h_last);

    float area = 0.5f * (hexp + hexp_n) * w;
    #pragma unroll
    for (int o = 16; o; o >>= 1) area += __shfl_xor_sync(0xffffffffu, area, o);
    const float inv_area = 1.0f / area;
    const float hl = hexp * inv_area;
    const float hr = hexp_n * inv_area;

    // --- inclusive scans: cdf over trapezoids, locs over widths ---
    float cdf = 0.5f * (hl + hr) * w;
    float loc = w;
    #pragma unroll
    for (int o = 1; o < 32; o <<= 1) {
        const float c = __shfl_up_sync(0xffffffffu, cdf, o);
        const float l = __shfl_up_sync(0xffffffffu, loc, o);
        if (lane >= o) { cdf += c; loc += l; }
    }
    float cdf_l = __shfl_up_sync(0xffffffffu, cdf, 1); if (lane == 0) cdf_l = 0.0f;
    float bl_l  = __shfl_up_sync(0xffffffffu, loc, 1); if (lane == 0) bl_l  = 0.0f;

    // --- 16B bin struct ---
    const float A = (hr - hl) / w;
    const float4 ebin = make_float4(bl_l, cdf_l, hl, A);
    g_bins16[r * NBINS + lane] = ebin;
    s_e[warp][lane]  = ebin;
    s_bl[warp][lane] = bl_l;
    if (lane == 31) s_bl[warp][32] = 1.0f;
    __syncwarp();

    // --- bucket-direct table: k_ub = max k<=31 with bl[k] <= (b+1)/128 ---
    float4* buckets = g_buckets + (size_t)r * NBUCKETS;
    #pragma unroll
    for (int j = 0; j < NBUCKETS / 32; j++) {
        const int b   = lane + j * 32;
        const float v = (float)(b + 1) * (1.0f / (float)NBUCKETS);  // exact
        int k = 0;
        #pragma unroll
        for (int st = 16; st >= 1; st >>= 1) {
            const int t = k + st;
            if (t <= 31 && s_bl[warp][t] <= v) k = t;
        }
        float4 ek = s_e[warp][k];
        ek.w = __uint_as_float((__float_as_uint(ek.w) & ~31u) | (unsigned)k);
        buckets[b] = ek;
    }
}

// ---------------------------------------------------------------------------
// Kernel 2: 8 points/thread. One divergent 16B load per point (fast path);
// fallback first-step loads issued in parallel, rare serial second steps.
// ---------------------------------------------------------------------------
__global__ void __launch_bounds__(256)
spline_eval_kernel(const float* __restrict__ x, const int* __restrict__ ix,
                   float* __restrict__ out, float* __restrict__ lad, int n)
{
    const int i0 = (blockIdx.x * blockDim.x + threadIdx.x) * PTS;
    if (i0 >= n) return;   // n % 8 == 0

    float xs[PTS];
    int   rs[PTS];
    #pragma unroll
    for (int v = 0; v < PTS / 4; v++) {
        const float4 xv = *reinterpret_cast<const float4*>(x + i0 + v * 4);
        const int4   rv = *reinterpret_cast<const int4*>(ix + i0 + v * 4);
        xs[v*4+0] = xv.x; xs[v*4+1] = xv.y; xs[v*4+2] = xv.z; xs[v*4+3] = xv.w;
        rs[v*4+0] = rv.x; rs[v*4+1] = rv.y; rs[v*4+2] = rv.z; rs[v*4+3] = rv.w;
    }

    // Stage 1: PTS independent bucket loads (MLP = 8)
    float4 e[PTS];
    #pragma unroll
    for (int j = 0; j < PTS; j++) {
        const int b = min((int)(xs[j] * (float)NBUCKETS), NBUCKETS - 1);
        e[j] = __ldg(g_buckets + (size_t)rs[j] * NBUCKETS + b);
    }

    // Stage 2: first-step refinement loads issued IN PARALLEL (predicated),
    // then ultra-rare serial extra steps.
    #pragma unroll
    for (int j = 0; j < PTS; j++) {
        // bucket stores upper-bound bin; x < bl_l means step back (k_ub >= 1 then)
        if (xs[j] < e[j].x) {
            int k = (int)(__float_as_uint(e[j].w) & 31u) - 1;
            e[j] = __ldg(g_bins16 + (size_t)rs[j] * NBINS + k);
            while (k > 0 && xs[j] < e[j].x) {          // ~0.3% of points
                k--;
                e[j] = __ldg(g_bins16 + (size_t)rs[j] * NBINS + k);
            }
        }
    }

    // Compute + store: out = cdf_l + t*(h_l + 0.5*A*t);  lad = log(h_l + A*t)
    #pragma unroll
    for (int v = 0; v < PTS / 4; v++) {
        float o[4], l[4];
        #pragma unroll
        for (int u = 0; u < 4; u++) {
            const int j = v * 4 + u;
            const float t = xs[j] - e[j].x;
            o[u] = fmaf(t, fmaf(0.5f * e[j].w, t, e[j].z), e[j].y);
            l[u] = __logf(fmaf(e[j].w, t, e[j].z));
        }
        *reinterpret_cast<float4*>(out + i0 + v * 4) = make_float4(o[0], o[1], o[2], o[3]);
        *reinterpret_cast<float4*>(lad + i0 + v * 4) = make_float4(l[0], l[1], l[2], l[3]);
    }
}

// ---------------------------------------------------------------------------
extern "C" void kernel_launch(void* const* d_in, const int* in_sizes, int n_in,
                              void* d_out, int out_size)
{
    const float* x  = (const float*)d_in[0];
    const int*   ix = (const int*)d_in[1];
    const float* uw = (const float*)d_in[2];
    const float* uh = (const float*)d_in[3];

    const int n = in_sizes[0];                   // 2,000,000 points
    float* out = (float*)d_out;                  // outputs[0:n]
    float* lad = (float*)d_out + n;              // logabsdet[n:2n]

    const int prep_blocks = (NREG + 7) / 8;
    spline_prep_kernel<<<prep_blocks, 256>>>(uw, uh);

    const int threads = 256;
    const int per_block = threads * PTS;
    const int eval_blocks = (n + per_block - 1) / per_block;
    spline_eval_kernel<<<eval_blocks, threads>>>(x, ix, out, lad, n);
}